// round 9
// baseline (speedup 1.0000x reference)
#include <cuda_runtime.h>
#include <cuda_fp16.h>
#include <math.h>

#define N_CAPS 64
#define IN_CAPS 4096
#define CAP_DIM 32
#define IN_DIM 16
#define EPS 1e-7f

#define GRID 148                 // all SMs; co-resident at occ 1 (capacity 148)
#define TPB 1024
#define NWARP 32
#define SEG_PAIRS 64
#define SEGS_PER_N 64            // 4096 pairs per n / 64
#define MAX_PAIRS (28 * SEG_PAIRS)              // 1792
#define SMEM_U_BYTES (MAX_PAIRS * CAP_DIM * 2)  // 114688 B fp16 u

// Partition: 4096 segments over 148 blocks = 100 blocks x 28 + 48 x 27.
__device__ __forceinline__ int seg_start(int b) { return 27 * b + (b < 100 ? b : 100); }
__device__ __forceinline__ int blk_of_seg(int s) {
    return (s < 2800) ? (s / 28) : (100 + (s - 2800) / 27);
}

// globals (allocation-free rule)
__device__ float g_psn[N_CAPS][4][CAP_DIM];   // partial S per (n, contributor slot)
__device__ float g_pzn[N_CAPS][4];            // partial Z
__device__ float g_v[N_CAPS * CAP_DIM];       // cumulative v
__device__ unsigned int g_cnt[3] = {0u, 0u, 0u};
__device__ unsigned int g_flag[2] = {0u, 0u};

__global__ void __launch_bounds__(TPB, 1)
caps_kernel(const float* __restrict__ W, const float* __restrict__ x,
            float* __restrict__ out)
{
    extern __shared__ unsigned int u_sm[];   // half2 words: [pair*16 + k] = dims 2k,2k+1
    __half* const u_h = reinterpret_cast<__half*>(u_sm);
    const int tid  = threadIdx.x;
    const int wid  = tid >> 5;
    const int lane = tid & 31;
    const int blk  = blockIdx.x;

    // block's pair range; may straddle ONE n boundary
    const int P0 = seg_start(blk) * SEG_PAIRS;
    const int C  = (27 + (blk < 100 ? 1 : 0)) * SEG_PAIRS;   // 1792 or 1728
    const int n0 = P0 >> 12;
    const int split = min(C, ((n0 + 1) << 12) - P0);         // local pairs in n0
    const bool has_n1 = (split < C);
    const int n1 = has_n1 ? (n0 + 1) : n0;
    const int j0 = blk - blk_of_seg(n0 * SEGS_PER_N);        // slot for n0 (0..3)

    __shared__ float  sm_A0[NWARP][CAP_DIM];
    __shared__ float  sm_A1[NWARP][CAP_DIM];
    __shared__ float2 sm_B0[NWARP][16];
    __shared__ float2 sm_B1[NWARP][16];
    __shared__ float  sm_z0[NWARP], sm_z1[NWARP];
    __shared__ float  sm_red[NWARP];
    __shared__ float  sm_scale;
    __shared__ unsigned int sm_last;

    // ---------------- Phase A: u = W.x, coalesced W stream (R8 scheme).
    // lane l loads float4 (j*32+l): k-chunk (l&3) of dim 8j+(l>>2); 4-lane
    // xor-reduce completes dots; lane keeps dim (l>>2)+8*(l&3).
    {
        const int PPWrt = C >> 5;           // 56 or 54 pairs per warp
        const int p0 = wid * PPWrt;
        const int m = lane >> 2, kc = lane & 3;
        const int mydim = m + 8 * kc;
        float A00 = 0.f, A01 = 0.f;
        const float4* wp = reinterpret_cast<const float4*>(W) + (size_t)(P0 + p0) * 128;
        const float4* x4 = reinterpret_cast<const float4*>(x);

#pragma unroll 2
        for (int p = 0; p < PPWrt; p++) {
            const float4* base = wp + p * 128;        // 128 float4s per pair
            float4 w0 = base[lane];
            float4 w1 = base[lane + 32];
            float4 w2 = base[lane + 64];
            float4 w3 = base[lane + 96];
            const int gp = p0 + p;                    // local pair index
            float4 xv = __ldg(x4 + (((P0 + gp) & (IN_CAPS - 1)) << 2) + kc);

            float d0 = w0.x*xv.x + w0.y*xv.y + w0.z*xv.z + w0.w*xv.w;
            float d1 = w1.x*xv.x + w1.y*xv.y + w1.z*xv.z + w1.w*xv.w;
            float d2 = w2.x*xv.x + w2.y*xv.y + w2.z*xv.z + w2.w*xv.w;
            float d3 = w3.x*xv.x + w3.y*xv.y + w3.z*xv.z + w3.w*xv.w;
            d0 += __shfl_xor_sync(0xffffffffu, d0, 1);
            d1 += __shfl_xor_sync(0xffffffffu, d1, 1);
            d2 += __shfl_xor_sync(0xffffffffu, d2, 1);
            d3 += __shfl_xor_sync(0xffffffffu, d3, 1);
            d0 += __shfl_xor_sync(0xffffffffu, d0, 2);
            d1 += __shfl_xor_sync(0xffffffffu, d1, 2);
            d2 += __shfl_xor_sync(0xffffffffu, d2, 2);
            d3 += __shfl_xor_sync(0xffffffffu, d3, 2);

            float u = (kc == 0) ? d0 : (kc == 1) ? d1 : (kc == 2) ? d2 : d3;
            if (gp < split) A00 += u; else A01 += u;
            u_h[gp * CAP_DIM + mydim] = __float2half_rn(u);
        }
        sm_A0[wid][mydim] = A00;
        sm_A1[wid][mydim] = A01;
    }
    __syncthreads();
    if (tid < CAP_DIM) {                    // n0 partial S (iter0: e == 1, exact fp32)
        float s = 0.f;
#pragma unroll
        for (int k = 0; k < NWARP; k++) s += sm_A0[k][tid];
        g_psn[n0][j0][tid] = s;
    } else if (tid >= 32 && tid < 64 && has_n1) {
        const int d = tid - 32;
        float s = 0.f;
#pragma unroll
        for (int k = 0; k < NWARP; k++) s += sm_A1[k][d];
        g_psn[n1][0][d] = s;               // boundary block is n1's first contributor
    }

    // ---------------- 3 routing iterations with software grid barrier
    for (int t = 0; t < 3; t++) {
        if (t > 0) {
            // Phase B from SMEM u. 64 half-warp groups; group h strides pairs
            // h, h+64, ... lane16 k owns dims 2k,2k+1. Per pair select v by n.
            const int l16 = lane & 15;
            const float2 vv0 = *reinterpret_cast<const float2*>(&g_v[n0 * CAP_DIM + 2 * l16]);
            const float2 vv1 = *reinterpret_cast<const float2*>(&g_v[n1 * CAP_DIM + 2 * l16]);
            float ax0 = 0.f, ay0 = 0.f, z0 = 0.f;
            float ax1 = 0.f, ay1 = 0.f, z1 = 0.f;

            for (int p = (tid >> 4); p < C; p += 64) {
                unsigned int wrd = u_sm[p * 16 + l16];
                __half2 h2 = *reinterpret_cast<__half2*>(&wrd);
                float2 uu = __half22float2(h2);
                const bool in0 = (p < split);
                const float2 vv = in0 ? vv0 : vv1;
                float dt = uu.x * vv.x + uu.y * vv.y;
                dt += __shfl_xor_sync(0xffffffffu, dt, 1);
                dt += __shfl_xor_sync(0xffffffffu, dt, 2);
                dt += __shfl_xor_sync(0xffffffffu, dt, 4);
                dt += __shfl_xor_sync(0xffffffffu, dt, 8);   // 16-lane dot
                float e = __expf(dt);
                if (in0) { ax0 += e * uu.x; ay0 += e * uu.y; z0 += e; }
                else     { ax1 += e * uu.x; ay1 += e * uu.y; z1 += e; }
            }
            // fold the two 16-lane groups of each warp together
            ax0 += __shfl_xor_sync(0xffffffffu, ax0, 16);
            ay0 += __shfl_xor_sync(0xffffffffu, ay0, 16);
            z0  += __shfl_xor_sync(0xffffffffu, z0, 16);
            ax1 += __shfl_xor_sync(0xffffffffu, ax1, 16);
            ay1 += __shfl_xor_sync(0xffffffffu, ay1, 16);
            z1  += __shfl_xor_sync(0xffffffffu, z1, 16);
            if (lane < 16) {
                sm_B0[wid][lane] = make_float2(ax0, ay0);
                sm_B1[wid][lane] = make_float2(ax1, ay1);
            }
            if (lane == 0) { sm_z0[wid] = z0; sm_z1[wid] = z1; }
            __syncthreads();

            if (tid < CAP_DIM) {
                const int k = tid >> 1, c = tid & 1;
                float s = 0.f;
#pragma unroll
                for (int w2 = 0; w2 < NWARP; w2++) {
                    float2 a = sm_B0[w2][k];
                    s += c ? a.y : a.x;
                }
                g_psn[n0][j0][tid] = s;
                if (tid == 0) {
                    float zt = 0.f;
#pragma unroll
                    for (int w2 = 0; w2 < NWARP; w2++) zt += sm_z0[w2];
                    g_pzn[n0][j0] = zt;     // per-lane z already equals group sums
                }
            } else if (tid >= 32 && tid < 64 && has_n1) {
                const int d = tid - 32, k = d >> 1, c = d & 1;
                float s = 0.f;
#pragma unroll
                for (int w2 = 0; w2 < NWARP; w2++) {
                    float2 a = sm_B1[w2][k];
                    s += c ? a.y : a.x;
                }
                g_psn[n1][0][d] = s;
                if (d == 0) {
                    float zt = 0.f;
#pragma unroll
                    for (int w2 = 0; w2 < NWARP; w2++) zt += sm_z1[w2];
                    g_pzn[n1][0] = zt;
                }
            }
        }

        // ---- arrive ----
        __threadfence();
        __syncthreads();
        if (tid == 0) {
            unsigned int prev = atomicAdd(&g_cnt[t], 1u);
            sm_last = (prev == GRID - 1) ? 1u : 0u;
        }
        __syncthreads();

        if (sm_last) {
            // ---- combine (deterministic fixed-order over contributor slots) ----
            __threadfence();
            float sr[2]; float sq = 0.f;
#pragma unroll
            for (int r = 0; r < 2; r++) {
                int idx = tid + r * TPB;        // idx = n2*32 + d  (2048 total)
                int n2 = idx >> 5, d = idx & 31;
                int fb = blk_of_seg(n2 * SEGS_PER_N);
                int span = blk_of_seg(n2 * SEGS_PER_N + SEGS_PER_N - 1) - fb + 1;
                float num = 0.f, Z = 0.f;
#pragma unroll
                for (int j = 0; j < 4; j++) {
                    if (j < span) {
                        num += g_psn[n2][j][d];
                        Z   += g_pzn[n2][j];
                    }
                }
                if (t == 0) Z = (float)IN_CAPS;   // e == 1 everywhere
                float s = num / Z;
                sr[r] = s; sq += s * s;
            }
#pragma unroll
            for (int o = 16; o > 0; o >>= 1) sq += __shfl_xor_sync(0xffffffffu, sq, o);
            if (lane == 0) sm_red[wid] = sq;
            __syncthreads();
            if (tid == 0) {
                float tt = 0.f;
#pragma unroll
                for (int k = 0; k < NWARP; k++) tt += sm_red[k];
                sm_scale = tt / (1.0f + tt) / (sqrtf(tt) + EPS);
            }
            __syncthreads();
            const float scale = sm_scale;
#pragma unroll
            for (int r = 0; r < 2; r++) {
                int idx = tid + r * TPB;
                float v = sr[r] * scale;
                if (t == 0)      g_v[idx] = v;       // overwrite: no init launch
                else if (t == 1) g_v[idx] += v;      // cumulative for iter 2
                else             out[idx] = v;       // final output
            }
            __threadfence();
            __syncthreads();
            if (tid == 0) {
                if (t < 2) {
                    atomicExch(&g_flag[t], 1u);      // release
                } else {
                    g_cnt[0] = 0u; g_cnt[1] = 0u; g_cnt[2] = 0u;   // replay reset
                    g_flag[0] = 0u; g_flag[1] = 0u;
                }
            }
        } else {
            if (t == 2) return;                      // partials written; done
            if (tid == 0) {
                while (atomicAdd(&g_flag[t], 0u) == 0u) __nanosleep(64);
            }
            __syncthreads();
            __threadfence();
        }
    }
}

// ---------------------------------------------------------------------------
extern "C" void kernel_launch(void* const* d_in, const int* in_sizes, int n_in,
                              void* d_out, int out_size) {
    const float* x = (const float*)d_in[0];
    const float* W = (const float*)d_in[1];
    if (in_sizes[0] > in_sizes[1]) { const float* t = x; x = W; W = t; }
    float* out = (float*)d_out;

    cudaFuncSetAttribute(caps_kernel,
                         cudaFuncAttributeMaxDynamicSharedMemorySize, SMEM_U_BYTES);
    caps_kernel<<<GRID, TPB, SMEM_U_BYTES>>>(W, x, out);
}

// round 10
// speedup vs baseline: 1.0301x; 1.0301x over previous
#include <cuda_runtime.h>
#include <cuda_fp16.h>
#include <math.h>

#define N_CAPS 64
#define IN_CAPS 4096
#define CAP_DIM 32
#define IN_DIM 16
#define EPS 1e-7f

#define GRID 128                 // <= 148 SMs: all blocks co-resident (1 block/SM)
#define TPB 1024
#define NWARP 32
#define PPB (N_CAPS * IN_CAPS / GRID)   // 2048 pairs per block
#define PPW (PPB / NWARP)               // 64 pairs per warp
#define SMEM_U_BYTES (PPB * CAP_DIM * 2)  // 131072 B of fp16 u

// globals (allocation-free rule)
__device__ float g_ps[GRID][CAP_DIM];     // per-block partial S
__device__ float g_pz[GRID];              // per-block partial Z
__device__ float g_v[N_CAPS * CAP_DIM];   // cumulative v
__device__ unsigned int g_cnt[3] = {0u, 0u, 0u};
__device__ unsigned int g_flag[2] = {0u, 0u};

__global__ void __launch_bounds__(TPB, 1)
caps_kernel(const float* __restrict__ W, const float* __restrict__ x,
            float* __restrict__ out)
{
    extern __shared__ unsigned int u_sm[];   // half2 words: [pair*16 + k] = dims 2k,2k+1
    __half* const u_h = reinterpret_cast<__half*>(u_sm);
    const int tid  = threadIdx.x;
    const int wid  = tid >> 5;
    const int lane = tid & 31;
    const int blk  = blockIdx.x;
    const int n     = blk >> 1;                      // 2 blocks per output capsule
    const int ibase = (blk & 1) * (IN_CAPS / 2);

    __shared__ float  sm_A[NWARP][CAP_DIM];
    __shared__ float2 sm_B[NWARP][CAP_DIM];
    __shared__ float  sm_z[NWARP];
    __shared__ float  sm_red[NWARP];
    __shared__ float  sm_scale;
    __shared__ unsigned int sm_last;

    // ---------------- Phase A: u = W.x, fully-coalesced streaming W reads with
    // an EXPLICIT register double-buffer: pair p+1's four 512B LDG.128 (__ldcs,
    // evict-first — W has zero reuse) are issued before pair p is consumed, so
    // every warp keeps >= 32 128B-lines in flight regardless of compiler
    // scheduling. Lane l holds k-chunk (l&3) of dim 8j+(l>>2); 4-lane
    // xor-reduce completes dots; lane keeps dim (l>>2)+8*(l&3). STS.U16 layout
    // is byte-identical to what Phase B reads.
    {
        const int p0  = wid * PPW;
        const int m   = lane >> 2;           // dim sub-index
        const int kc  = lane & 3;            // k-chunk
        const int mydim = m + 8 * kc;        // dim this lane stores/accumulates
        float A0 = 0.f;

        const float4* wp = reinterpret_cast<const float4*>(
            W + (size_t)(n * IN_CAPS + ibase + p0) * (CAP_DIM * IN_DIM));
        const float4* xp = reinterpret_cast<const float4*>(
            x + (size_t)(ibase + p0) * IN_DIM);

        // preload pair 0
        float4 a0 = __ldcs(wp + lane);
        float4 a1 = __ldcs(wp + lane + 32);
        float4 a2 = __ldcs(wp + lane + 64);
        float4 a3 = __ldcs(wp + lane + 96);

        for (int p = 0; p < PPW; p++) {
            // issue next pair's loads first (clamped on last iteration)
            const float4* nb = wp + (p + 1 < PPW ? (p + 1) : p) * 128;
            float4 b0 = __ldcs(nb + lane);
            float4 b1 = __ldcs(nb + lane + 32);
            float4 b2 = __ldcs(nb + lane + 64);
            float4 b3 = __ldcs(nb + lane + 96);

            float4 xv = __ldg(xp + p * 4 + kc);       // this lane's k-chunk of x

            float d0 = a0.x * xv.x + a0.y * xv.y + a0.z * xv.z + a0.w * xv.w; // dim m
            float d1 = a1.x * xv.x + a1.y * xv.y + a1.z * xv.z + a1.w * xv.w; // dim m+8
            float d2 = a2.x * xv.x + a2.y * xv.y + a2.z * xv.z + a2.w * xv.w; // dim m+16
            float d3 = a3.x * xv.x + a3.y * xv.y + a3.z * xv.z + a3.w * xv.w; // dim m+24

            d0 += __shfl_xor_sync(0xffffffffu, d0, 1);
            d1 += __shfl_xor_sync(0xffffffffu, d1, 1);
            d2 += __shfl_xor_sync(0xffffffffu, d2, 1);
            d3 += __shfl_xor_sync(0xffffffffu, d3, 1);
            d0 += __shfl_xor_sync(0xffffffffu, d0, 2);
            d1 += __shfl_xor_sync(0xffffffffu, d1, 2);
            d2 += __shfl_xor_sync(0xffffffffu, d2, 2);
            d3 += __shfl_xor_sync(0xffffffffu, d3, 2);

            float u = (kc == 0) ? d0 : (kc == 1) ? d1 : (kc == 2) ? d2 : d3;
            A0 += u;
            u_h[(p0 + p) * CAP_DIM + mydim] = __float2half_rn(u);

            a0 = b0; a1 = b1; a2 = b2; a3 = b3;
        }
        sm_A[wid][mydim] = A0;
    }
    __syncthreads();
    if (tid < CAP_DIM) {                    // block partial S (iter0: e == 1, exact fp32)
        float s = 0.f;
#pragma unroll
        for (int k = 0; k < NWARP; k++) s += sm_A[k][tid];
        g_ps[blk][tid] = s;
    }

    // ---------------- 3 routing iterations with software grid barrier
    for (int t = 0; t < 3; t++) {
        if (t > 0) {
            // Phase B: partials from SMEM u. lane k=lane&15 owns dims 2k,2k+1;
            // lanes 0-15 process even pair offsets, 16-31 odd offsets.
            const float2 vv = *reinterpret_cast<const float2*>(
                &g_v[n * CAP_DIM + 2 * (lane & 15)]);
            float ax = 0.f, ay = 0.f, z = 0.f;
            const int pbase = wid * PPW + ((lane >> 4) & 1);
#pragma unroll 4
            for (int s2 = 0; s2 < PPW / 2; s2++) {
                unsigned int wrd = u_sm[(pbase + 2 * s2) * 16 + (lane & 15)];
                __half2 h = *reinterpret_cast<__half2*>(&wrd);
                float2 uu = __half22float2(h);
                float dt = uu.x * vv.x + uu.y * vv.y;
                dt += __shfl_xor_sync(0xffffffffu, dt, 1);
                dt += __shfl_xor_sync(0xffffffffu, dt, 2);
                dt += __shfl_xor_sync(0xffffffffu, dt, 4);
                dt += __shfl_xor_sync(0xffffffffu, dt, 8);   // 16-lane group dot
                float e = __expf(dt);
                ax += e * uu.x; ay += e * uu.y; z += e;
            }
            sm_B[wid][lane] = make_float2(ax, ay);
#pragma unroll
            for (int o = 16; o > 0; o >>= 1) z += __shfl_xor_sync(0xffffffffu, z, o);
            if (lane == 0) sm_z[wid] = z;
            __syncthreads();
            if (tid < CAP_DIM) {
                const int k = tid >> 1, j = tid & 1;
                float s = 0.f;
#pragma unroll
                for (int w2 = 0; w2 < NWARP; w2++) {
                    float2 a = sm_B[w2][k];
                    float2 b2 = sm_B[w2][k + 16];
                    s += j ? (a.y + b2.y) : (a.x + b2.x);
                }
                g_ps[blk][tid] = s;
            } else if (tid == CAP_DIM) {
                float zt = 0.f;
#pragma unroll
                for (int w2 = 0; w2 < NWARP; w2++) zt += sm_z[w2];
                g_pz[blk] = zt * (1.f / 16.f);   // each pair's e counted 16x
            }
        }

        // ---- arrive ----
        __threadfence();
        __syncthreads();
        if (tid == 0) {
            unsigned int prev = atomicAdd(&g_cnt[t], 1u);
            sm_last = (prev == GRID - 1) ? 1u : 0u;
        }
        __syncthreads();

        if (sm_last) {
            // ---- combine (deterministic fixed-order reduction) ----
            __threadfence();
            float sr[2]; float sq = 0.f;
#pragma unroll
            for (int r = 0; r < 2; r++) {
                int idx = tid + r * TPB;        // idx = n2*32 + d  (2048 total)
                int n2 = idx >> 5, d = idx & 31;
                float num = g_ps[2 * n2][d] + g_ps[2 * n2 + 1][d];
                float Z = (t == 0) ? (float)IN_CAPS : (g_pz[2 * n2] + g_pz[2 * n2 + 1]);
                float s = num / Z;
                sr[r] = s; sq += s * s;
            }
#pragma unroll
            for (int o = 16; o > 0; o >>= 1) sq += __shfl_xor_sync(0xffffffffu, sq, o);
            if (lane == 0) sm_red[wid] = sq;
            __syncthreads();
            if (tid == 0) {
                float tt = 0.f;
#pragma unroll
                for (int k = 0; k < NWARP; k++) tt += sm_red[k];
                sm_scale = tt / (1.0f + tt) / (sqrtf(tt) + EPS);
            }
            __syncthreads();
            const float scale = sm_scale;
#pragma unroll
            for (int r = 0; r < 2; r++) {
                int idx = tid + r * TPB;
                float v = sr[r] * scale;
                if (t == 0)      g_v[idx] = v;       // overwrite: no init launch
                else if (t == 1) g_v[idx] += v;      // cumulative for iter 2
                else             out[idx] = v;       // final output
            }
            __threadfence();
            __syncthreads();
            if (tid == 0) {
                if (t < 2) {
                    atomicExch(&g_flag[t], 1u);      // release
                } else {
                    g_cnt[0] = 0u; g_cnt[1] = 0u; g_cnt[2] = 0u;   // replay reset
                    g_flag[0] = 0u; g_flag[1] = 0u;
                }
            }
        } else {
            if (t == 2) return;                      // partials written; done
            if (tid == 0) {
                while (atomicAdd(&g_flag[t], 0u) == 0u) __nanosleep(64);
            }
            __syncthreads();
            __threadfence();
        }
    }
}

// ---------------------------------------------------------------------------
extern "C" void kernel_launch(void* const* d_in, const int* in_sizes, int n_in,
                              void* d_out, int out_size) {
    const float* x = (const float*)d_in[0];
    const float* W = (const float*)d_in[1];
    if (in_sizes[0] > in_sizes[1]) { const float* t = x; x = W; W = t; }
    float* out = (float*)d_out;

    cudaFuncSetAttribute(caps_kernel,
                         cudaFuncAttributeMaxDynamicSharedMemorySize, SMEM_U_BYTES);
    caps_kernel<<<GRID, TPB, SMEM_U_BYTES>>>(W, x, out);
}